// round 3
// baseline (speedup 1.0000x reference)
#include <cuda_runtime.h>

#define NN 100000
#define NE 1600000
#define IND 128
#define HD 64

// -------- scratch (no allocation allowed: __device__ globals) --------
__device__ float g_norm_src[NN];               // degree accumulator -> rsqrt norm
__device__ float g_norm_dst[NN];
__device__ __align__(16) float g_x1[NN * HD];  // projected layer-1 features
__device__ __align__(16) float g_agg1[NN * HD];// layer-1 aggregation
__device__ __align__(16) float g_x2[NN * HD];  // projected layer-2 features

// -------- init: zero degree counters, agg1, and d_out --------
__global__ void k_init(float4* __restrict__ out4) {
    int i = blockIdx.x * blockDim.x + threadIdx.x;
    int stride = gridDim.x * blockDim.x;
    for (int j = i; j < NN; j += stride) {
        g_norm_src[j] = 0.f;
        g_norm_dst[j] = 0.f;
    }
    float4 z = make_float4(0.f, 0.f, 0.f, 0.f);
    float4* agg4 = reinterpret_cast<float4*>(g_agg1);
    for (int j = i; j < NN * (HD / 4); j += stride) {
        agg4[j] = z;
        out4[j] = z;
    }
}

// -------- degrees --------
__global__ void k_deg(const int* __restrict__ src, const int* __restrict__ dst) {
    int i = blockIdx.x * blockDim.x + threadIdx.x;
    if (i < NE) {
        atomicAdd(&g_norm_src[src[i]], 1.f);
        atomicAdd(&g_norm_dst[dst[i]], 1.f);
    }
}

// -------- norms: deg -> rsqrt(max(deg,1)) --------
__global__ void k_norm() {
    int i = blockIdx.x * blockDim.x + threadIdx.x;
    if (i < NN) {
        g_norm_src[i] = rsqrtf(fmaxf(g_norm_src[i], 1.f));
        g_norm_dst[i] = rsqrtf(fmaxf(g_norm_dst[i], 1.f));
    }
}

// -------- GEMM1: g_x1 = (h * norm_src) @ W1   [100000x128 @ 128x64] --------
// block = 256 threads = 16 rows x 16 col-quads. W1 (32KB) + 16 h-rows (8KB) in smem.
__global__ __launch_bounds__(256) void k_gemm1(const float* __restrict__ h,
                                               const float* __restrict__ W1) {
    __shared__ float Ws[IND * HD];   // 32 KB, [k][c]
    __shared__ float hs[16 * IND];   // 8 KB
    int tid = threadIdx.x;
    for (int i = tid; i < IND * HD; i += 256) Ws[i] = W1[i];

    int r = tid >> 4;        // 0..15 local row
    int c4 = tid & 15;       // 0..15 column quad

    for (int row0 = blockIdx.x * 16; row0 < NN; row0 += gridDim.x * 16) {
        __syncthreads();
        // stage 16 contiguous rows of h (2048 floats, coalesced)
        for (int i = tid; i < 16 * IND; i += 256) hs[i] = h[row0 * IND + i];
        __syncthreads();

        const float* hr = &hs[r * IND];
        float4 acc = make_float4(0.f, 0.f, 0.f, 0.f);
#pragma unroll
        for (int k = 0; k < IND; k++) {
            float hv = hr[k];                                        // broadcast LDS
            float4 w = reinterpret_cast<const float4*>(Ws + k * HD)[c4];  // LDS.128
            acc.x = fmaf(hv, w.x, acc.x);
            acc.y = fmaf(hv, w.y, acc.y);
            acc.z = fmaf(hv, w.z, acc.z);
            acc.w = fmaf(hv, w.w, acc.w);
        }
        int row = row0 + r;
        float s = g_norm_src[row];
        float4 o = make_float4(acc.x * s, acc.y * s, acc.z * s, acc.w * s);
        reinterpret_cast<float4*>(g_x1)[row * (HD / 4) + c4] = o;
    }
}

// -------- edge scatter: agg[dst] += x[src]  (16 lanes/edge, v4 red) --------
__device__ __forceinline__ void edge_body(const int* __restrict__ src,
                                          const int* __restrict__ dst,
                                          const float* __restrict__ x,
                                          float* __restrict__ agg) {
    int t = blockIdx.x * blockDim.x + threadIdx.x;
    int e = t >> 4;
    int lane = t & 15;
    if (e < NE) {
        int s = __ldg(&src[e]);
        int d = __ldg(&dst[e]);
        float4 v = __ldg(reinterpret_cast<const float4*>(x + s * HD) + lane);
        float* p = agg + d * HD + lane * 4;
        asm volatile("red.global.add.v4.f32 [%0], {%1, %2, %3, %4};"
                     :: "l"(p), "f"(v.x), "f"(v.y), "f"(v.z), "f"(v.w)
                     : "memory");
    }
}

__global__ __launch_bounds__(256) void k_edge1(const int* __restrict__ src,
                                               const int* __restrict__ dst) {
    edge_body(src, dst, g_x1, g_agg1);
}

__global__ __launch_bounds__(256) void k_edge2(const int* __restrict__ src,
                                               const int* __restrict__ dst,
                                               float* __restrict__ out) {
    edge_body(src, dst, g_x2, out);
}

// -------- GEMM2: g_x2 = (elu(agg1*norm_dst + b1) * norm_src) @ W2  [64x64] --------
__global__ __launch_bounds__(256) void k_gemm2(const float* __restrict__ b1,
                                               const float* __restrict__ W2) {
    __shared__ float Ws[HD * HD];   // 16 KB
    __shared__ float ts[16 * HD];   // 4 KB
    int tid = threadIdx.x;
    for (int i = tid; i < HD * HD; i += 256) Ws[i] = W2[i];

    int r = tid >> 4;
    int c4 = tid & 15;

    for (int row0 = blockIdx.x * 16; row0 < NN; row0 += gridDim.x * 16) {
        __syncthreads();
        // stage + fused epilogue of layer 1: elu(agg*nd + b1) * ns
        for (int i = tid; i < 16 * HD; i += 256) {
            int row = row0 + (i >> 6);
            int c = i & 63;
            float v = g_agg1[row0 * HD + i] * g_norm_dst[row] + b1[c];
            v = (v > 0.f) ? v : expm1f(v);
            ts[i] = v * g_norm_src[row];
        }
        __syncthreads();

        const float* tr = &ts[r * HD];
        float4 acc = make_float4(0.f, 0.f, 0.f, 0.f);
#pragma unroll
        for (int k = 0; k < HD; k++) {
            float tv = tr[k];
            float4 w = reinterpret_cast<const float4*>(Ws + k * HD)[c4];
            acc.x = fmaf(tv, w.x, acc.x);
            acc.y = fmaf(tv, w.y, acc.y);
            acc.z = fmaf(tv, w.z, acc.z);
            acc.w = fmaf(tv, w.w, acc.w);
        }
        int row = row0 + r;
        reinterpret_cast<float4*>(g_x2)[row * (HD / 4) + c4] = acc;
    }
}

// -------- finalize: out = out * norm_dst + b2 --------
__global__ __launch_bounds__(256) void k_final(float* __restrict__ out,
                                               const float* __restrict__ b2) {
    int i = blockIdx.x * blockDim.x + threadIdx.x;
    if (i < NN * (HD / 4)) {
        int row = i >> 4;
        int c4 = i & 15;
        float nd = g_norm_dst[row];
        float4 v = reinterpret_cast<float4*>(out)[i];
        float4 bb = __ldg(reinterpret_cast<const float4*>(b2) + c4);
        v.x = v.x * nd + bb.x;
        v.y = v.y * nd + bb.y;
        v.z = v.z * nd + bb.z;
        v.w = v.w * nd + bb.w;
        reinterpret_cast<float4*>(out)[i] = v;
    }
}

extern "C" void kernel_launch(void* const* d_in, const int* in_sizes, int n_in,
                              void* d_out, int out_size) {
    const float* h   = (const float*)d_in[0];
    const int*   src = (const int*)d_in[1];
    const int*   dst = (const int*)d_in[2];
    const float* W1  = (const float*)d_in[3];
    const float* b1  = (const float*)d_in[4];
    const float* W2  = (const float*)d_in[5];
    const float* b2  = (const float*)d_in[6];
    float* out = (float*)d_out;

    k_init<<<1184, 256>>>(reinterpret_cast<float4*>(out));
    k_deg<<<(NE + 255) / 256, 256>>>(src, dst);
    k_norm<<<(NN + 255) / 256, 256>>>();

    // layer 1
    k_gemm1<<<NN / 16, 256>>>(h, W1);
    k_edge1<<<(NE * 16) / 256, 256>>>(src, dst);

    // layer 2 (epilogue of layer1 + ELU fused into gemm2 staging)
    k_gemm2<<<NN / 16, 256>>>(b1, W2);
    k_edge2<<<(NE * 16) / 256, 256>>>(src, dst, out);

    k_final<<<(NN * 16 + 255) / 256, 256>>>(out, b2);
}

// round 4
// speedup vs baseline: 1.2395x; 1.2395x over previous
#include <cuda_runtime.h>

#define NN 100000
#define NE 1600000
#define IND 128
#define HD 64

// -------- scratch (no allocation allowed: __device__ globals) --------
__device__ float g_norm_src[NN];               // degree accumulator -> rsqrt norm
__device__ float g_norm_dst[NN];
__device__ __align__(16) float g_x1[NN * HD];  // projected layer-1 features
__device__ __align__(16) float g_agg1[NN * HD];// layer-1 aggregation
__device__ __align__(16) float g_x2[NN * HD];  // projected layer-2 features

// -------- init: zero degree counters, agg1, and d_out --------
__global__ void k_init(float4* __restrict__ out4) {
    int i = blockIdx.x * blockDim.x + threadIdx.x;
    int stride = gridDim.x * blockDim.x;
    for (int j = i; j < NN; j += stride) {
        g_norm_src[j] = 0.f;
        g_norm_dst[j] = 0.f;
    }
    float4 z = make_float4(0.f, 0.f, 0.f, 0.f);
    float4* agg4 = reinterpret_cast<float4*>(g_agg1);
    for (int j = i; j < NN * (HD / 4); j += stride) {
        agg4[j] = z;
        out4[j] = z;
    }
}

// -------- degrees --------
__global__ void k_deg(const int* __restrict__ src, const int* __restrict__ dst) {
    int i = blockIdx.x * blockDim.x + threadIdx.x;
    if (i < NE) {
        atomicAdd(&g_norm_src[src[i]], 1.f);
        atomicAdd(&g_norm_dst[dst[i]], 1.f);
    }
}

// -------- norms: deg -> rsqrt(max(deg,1)) --------
__global__ void k_norm() {
    int i = blockIdx.x * blockDim.x + threadIdx.x;
    if (i < NN) {
        g_norm_src[i] = rsqrtf(fmaxf(g_norm_src[i], 1.f));
        g_norm_dst[i] = rsqrtf(fmaxf(g_norm_dst[i], 1.f));
    }
}

// ============================================================================
// GEMM1: g_x1 = (h * norm_src) @ W1   [100000x128 @ 128x64]
// 64-row x 64-col tile per block, 256 threads, 4x4 register tile per thread.
// Activation tile transposed in smem (hsT[k][r], row-stride 65 -> bank-clean).
// K staged in 2 chunks of 64 to stay under 48KB static smem.
// ============================================================================
#define KC 64      // k-chunk
#define HSTR 65    // padded row stride for transposed tile

__global__ __launch_bounds__(256) void k_gemm1(const float* __restrict__ h,
                                               const float* __restrict__ W1) {
    __shared__ __align__(16) float Wc[KC * HD];      // 16 KB  [kk][c]
    __shared__ float hsT[KC * HSTR];                 // 16.25 KB [kk][r]
    int tid = threadIdx.x;
    int ty = tid >> 4;      // 0..15 -> rows 4*ty..4*ty+3
    int tx = tid & 15;      // 0..15 -> cols 4*tx..4*tx+3
    int row0 = blockIdx.x * 64;

    float acc[4][4];
#pragma unroll
    for (int j = 0; j < 4; j++)
#pragma unroll
        for (int c = 0; c < 4; c++) acc[j][c] = 0.f;

#pragma unroll
    for (int kc = 0; kc < IND / KC; kc++) {
        int k0 = kc * KC;
        __syncthreads();
        // stage W chunk: 4096 floats, coalesced
        for (int i = tid; i < KC * HD; i += 256)
            Wc[i] = W1[k0 * HD + i];
        // stage h chunk transposed: lanes sweep kk (coalesced gmem),
        // STS banks (65*kk + r) % 32 all distinct -> conflict-free
        for (int i = tid; i < 64 * KC; i += 256) {
            int r = i >> 6;          // 0..63
            int kk = i & (KC - 1);   // 0..63
            int row = row0 + r;
            float v = (row < NN) ? h[row * IND + k0 + kk] : 0.f;
            hsT[kk * HSTR + r] = v;
        }
        __syncthreads();

        const float* hp = &hsT[4 * ty];
        const float4* wq = reinterpret_cast<const float4*>(Wc) + tx;
#pragma unroll 8
        for (int kk = 0; kk < KC; kk++) {
            float a0 = hp[0], a1 = hp[1], a2 = hp[2], a3 = hp[3];
            hp += HSTR;
            float4 w = wq[kk * (HD / 4)];
            acc[0][0] = fmaf(a0, w.x, acc[0][0]);
            acc[0][1] = fmaf(a0, w.y, acc[0][1]);
            acc[0][2] = fmaf(a0, w.z, acc[0][2]);
            acc[0][3] = fmaf(a0, w.w, acc[0][3]);
            acc[1][0] = fmaf(a1, w.x, acc[1][0]);
            acc[1][1] = fmaf(a1, w.y, acc[1][1]);
            acc[1][2] = fmaf(a1, w.z, acc[1][2]);
            acc[1][3] = fmaf(a1, w.w, acc[1][3]);
            acc[2][0] = fmaf(a2, w.x, acc[2][0]);
            acc[2][1] = fmaf(a2, w.y, acc[2][1]);
            acc[2][2] = fmaf(a2, w.z, acc[2][2]);
            acc[2][3] = fmaf(a2, w.w, acc[2][3]);
            acc[3][0] = fmaf(a3, w.x, acc[3][0]);
            acc[3][1] = fmaf(a3, w.y, acc[3][1]);
            acc[3][2] = fmaf(a3, w.z, acc[3][2]);
            acc[3][3] = fmaf(a3, w.w, acc[3][3]);
        }
    }

#pragma unroll
    for (int j = 0; j < 4; j++) {
        int row = row0 + 4 * ty + j;
        if (row < NN) {
            float s = g_norm_src[row];
            float4 o = make_float4(acc[j][0] * s, acc[j][1] * s,
                                   acc[j][2] * s, acc[j][3] * s);
            reinterpret_cast<float4*>(g_x1)[row * (HD / 4) + tx] = o;
        }
    }
}

// ============================================================================
// GEMM2: g_x2 = (elu(agg1*norm_dst + b1) * norm_src) @ W2  [100000x64 @ 64x64]
// Same 64x64 tile / 4x4 thread layout; layer-1 epilogue fused into staging.
// ============================================================================
__global__ __launch_bounds__(256) void k_gemm2(const float* __restrict__ b1,
                                               const float* __restrict__ W2) {
    __shared__ __align__(16) float Wc[HD * HD];      // 16 KB
    __shared__ float tsT[HD * HSTR];                 // 16.25 KB
    __shared__ float b1s[HD];
    int tid = threadIdx.x;
    int ty = tid >> 4;
    int tx = tid & 15;
    int row0 = blockIdx.x * 64;

    for (int i = tid; i < HD * HD; i += 256) Wc[i] = W2[i];
    if (tid < HD) b1s[tid] = b1[tid];
    __syncthreads();

    // stage + fused layer-1 epilogue: elu(agg*nd + b1) * ns, transposed store
    for (int i = tid; i < 64 * HD; i += 256) {
        int r = i >> 6;
        int k = i & (HD - 1);
        int row = row0 + r;
        float v = 0.f;
        if (row < NN) {
            v = g_agg1[row * HD + k] * g_norm_dst[row] + b1s[k];
            v = (v > 0.f) ? v : expm1f(v);
            v *= g_norm_src[row];
        }
        tsT[k * HSTR + r] = v;
    }
    __syncthreads();

    float acc[4][4];
#pragma unroll
    for (int j = 0; j < 4; j++)
#pragma unroll
        for (int c = 0; c < 4; c++) acc[j][c] = 0.f;

    const float* tp = &tsT[4 * ty];
    const float4* wq = reinterpret_cast<const float4*>(Wc) + tx;
#pragma unroll 8
    for (int k = 0; k < HD; k++) {
        float a0 = tp[0], a1 = tp[1], a2 = tp[2], a3 = tp[3];
        tp += HSTR;
        float4 w = wq[k * (HD / 4)];
        acc[0][0] = fmaf(a0, w.x, acc[0][0]);
        acc[0][1] = fmaf(a0, w.y, acc[0][1]);
        acc[0][2] = fmaf(a0, w.z, acc[0][2]);
        acc[0][3] = fmaf(a0, w.w, acc[0][3]);
        acc[1][0] = fmaf(a1, w.x, acc[1][0]);
        acc[1][1] = fmaf(a1, w.y, acc[1][1]);
        acc[1][2] = fmaf(a1, w.z, acc[1][2]);
        acc[1][3] = fmaf(a1, w.w, acc[1][3]);
        acc[2][0] = fmaf(a2, w.x, acc[2][0]);
        acc[2][1] = fmaf(a2, w.y, acc[2][1]);
        acc[2][2] = fmaf(a2, w.z, acc[2][2]);
        acc[2][3] = fmaf(a2, w.w, acc[2][3]);
        acc[3][0] = fmaf(a3, w.x, acc[3][0]);
        acc[3][1] = fmaf(a3, w.y, acc[3][1]);
        acc[3][2] = fmaf(a3, w.z, acc[3][2]);
        acc[3][3] = fmaf(a3, w.w, acc[3][3]);
    }

#pragma unroll
    for (int j = 0; j < 4; j++) {
        int row = row0 + 4 * ty + j;
        if (row < NN) {
            float4 o = make_float4(acc[j][0], acc[j][1], acc[j][2], acc[j][3]);
            reinterpret_cast<float4*>(g_x2)[row * (HD / 4) + tx] = o;
        }
    }
}

// -------- edge scatter: agg[dst] += x[src]  (16 lanes/edge, v4 red) --------
__device__ __forceinline__ void edge_body(const int* __restrict__ src,
                                          const int* __restrict__ dst,
                                          const float* __restrict__ x,
                                          float* __restrict__ agg) {
    int t = blockIdx.x * blockDim.x + threadIdx.x;
    int e = t >> 4;
    int lane = t & 15;
    if (e < NE) {
        int s = __ldg(&src[e]);
        int d = __ldg(&dst[e]);
        float4 v = __ldg(reinterpret_cast<const float4*>(x + s * HD) + lane);
        float* p = agg + d * HD + lane * 4;
        asm volatile("red.global.add.v4.f32 [%0], {%1, %2, %3, %4};"
                     :: "l"(p), "f"(v.x), "f"(v.y), "f"(v.z), "f"(v.w)
                     : "memory");
    }
}

__global__ __launch_bounds__(256) void k_edge1(const int* __restrict__ src,
                                               const int* __restrict__ dst) {
    edge_body(src, dst, g_x1, g_agg1);
}

__global__ __launch_bounds__(256) void k_edge2(const int* __restrict__ src,
                                               const int* __restrict__ dst,
                                               float* __restrict__ out) {
    edge_body(src, dst, g_x2, out);
}

// -------- finalize: out = out * norm_dst + b2 --------
__global__ __launch_bounds__(256) void k_final(float* __restrict__ out,
                                               const float* __restrict__ b2) {
    int i = blockIdx.x * blockDim.x + threadIdx.x;
    if (i < NN * (HD / 4)) {
        int row = i >> 4;
        int c4 = i & 15;
        float nd = g_norm_dst[row];
        float4 v = reinterpret_cast<float4*>(out)[i];
        float4 bb = __ldg(reinterpret_cast<const float4*>(b2) + c4);
        v.x = v.x * nd + bb.x;
        v.y = v.y * nd + bb.y;
        v.z = v.z * nd + bb.z;
        v.w = v.w * nd + bb.w;
        reinterpret_cast<float4*>(out)[i] = v;
    }
}

extern "C" void kernel_launch(void* const* d_in, const int* in_sizes, int n_in,
                              void* d_out, int out_size) {
    const float* h   = (const float*)d_in[0];
    const int*   src = (const int*)d_in[1];
    const int*   dst = (const int*)d_in[2];
    const float* W1  = (const float*)d_in[3];
    const float* b1  = (const float*)d_in[4];
    const float* W2  = (const float*)d_in[5];
    const float* b2  = (const float*)d_in[6];
    float* out = (float*)d_out;

    const int GBLK = (NN + 63) / 64;  // 1563

    k_init<<<1184, 256>>>(reinterpret_cast<float4*>(out));
    k_deg<<<(NE + 255) / 256, 256>>>(src, dst);
    k_norm<<<(NN + 255) / 256, 256>>>();

    // layer 1
    k_gemm1<<<GBLK, 256>>>(h, W1);
    k_edge1<<<(NE * 16) / 256, 256>>>(src, dst);

    // layer 2 (epilogue of layer1 + ELU fused into gemm2 staging)
    k_gemm2<<<GBLK, 256>>>(b1, W2);
    k_edge2<<<(NE * 16) / 256, 256>>>(src, dst, out);

    k_final<<<(NN * 16 + 255) / 256, 256>>>(out, b2);
}

// round 6
// speedup vs baseline: 1.7618x; 1.4213x over previous
#include <cuda_runtime.h>

#define NN 100000
#define NE 1600000
#define IND 128
#define HD 64
#define SCAN_BLOCKS 391   // ceil(NN/256)

// -------- scratch (no allocation allowed: __device__ globals) --------
__device__ int   g_deg_out[NN];
__device__ int   g_deg_in[NN];
__device__ int   g_start[NN];     // CSR row start (exclusive scan of deg_in)
__device__ int   g_cursor[NN];    // placement cursors
__device__ int   g_bsum[SCAN_BLOCKS];
__device__ int   g_esrc[NE];      // edge sources grouped by dst
__device__ float g_norm_src[NN];
__device__ float g_norm_dst[NN];
__device__ __align__(16) float g_x1[NN * HD];   // projected layer-1 features
__device__ __align__(16) float g_agg1[NN * HD]; // layer-1 aggregation
__device__ __align__(16) float g_x2[NN * HD];   // projected layer-2 features

// -------- init: zero integer degree counters --------
__global__ void k_init() {
    int i = blockIdx.x * blockDim.x + threadIdx.x;
    if (i < NN) {
        g_deg_out[i] = 0;
        g_deg_in[i] = 0;
    }
}

// -------- integer degree histograms --------
__global__ void k_deg(const int* __restrict__ src, const int* __restrict__ dst) {
    int i = blockIdx.x * blockDim.x + threadIdx.x;
    if (i < NE) {
        atomicAdd(&g_deg_out[src[i]], 1);
        atomicAdd(&g_deg_in[dst[i]], 1);
    }
}

// -------- norms from integer degrees --------
__global__ void k_norm() {
    int i = blockIdx.x * blockDim.x + threadIdx.x;
    if (i < NN) {
        g_norm_src[i] = rsqrtf(fmaxf((float)g_deg_out[i], 1.f));
        g_norm_dst[i] = rsqrtf(fmaxf((float)g_deg_in[i], 1.f));
    }
}

// -------- exclusive scan of deg_in -> g_start (3 kernels) --------
__global__ void k_scan1() {
    __shared__ int s[256];
    int tid = threadIdx.x;
    int i = blockIdx.x * 256 + tid;
    int v = (i < NN) ? g_deg_in[i] : 0;
    s[tid] = v;
    __syncthreads();
    for (int off = 1; off < 256; off <<= 1) {
        int t = (tid >= off) ? s[tid - off] : 0;
        __syncthreads();
        s[tid] += t;
        __syncthreads();
    }
    if (i < NN) g_start[i] = s[tid] - v;          // block-local exclusive
    if (tid == 255) g_bsum[blockIdx.x] = s[255];  // block total
}

__global__ void k_scan2() {  // single block of 512: exclusive scan of block sums
    __shared__ int s[512];
    int tid = threadIdx.x;
    int v = (tid < SCAN_BLOCKS) ? g_bsum[tid] : 0;
    s[tid] = v;
    __syncthreads();
    for (int off = 1; off < 512; off <<= 1) {
        int t = (tid >= off) ? s[tid - off] : 0;
        __syncthreads();
        s[tid] += t;
        __syncthreads();
    }
    if (tid < SCAN_BLOCKS) g_bsum[tid] = s[tid] - v;  // exclusive
}

__global__ void k_scan3() {
    int i = blockIdx.x * blockDim.x + threadIdx.x;
    if (i < NN) {
        int st = g_start[i] + g_bsum[i >> 8];
        g_start[i] = st;
        g_cursor[i] = st;
    }
}

// -------- CSR placement: group edge sources by dst --------
__global__ void k_place(const int* __restrict__ src, const int* __restrict__ dst) {
    int i = blockIdx.x * blockDim.x + threadIdx.x;
    if (i < NE) {
        int d = dst[i];
        int pos = atomicAdd(&g_cursor[d], 1);
        g_esrc[pos] = src[i];
    }
}

// ============================================================================
// GEMM1: g_x1 = (h * norm_src) @ W1   [100000x128 @ 128x64]
// ============================================================================
#define KC 64
#define HSTR 65

__global__ __launch_bounds__(256) void k_gemm1(const float* __restrict__ h,
                                               const float* __restrict__ W1) {
    __shared__ __align__(16) float Wc[KC * HD];
    __shared__ float hsT[KC * HSTR];
    int tid = threadIdx.x;
    int ty = tid >> 4;
    int tx = tid & 15;
    int row0 = blockIdx.x * 64;

    float acc[4][4];
#pragma unroll
    for (int j = 0; j < 4; j++)
#pragma unroll
        for (int c = 0; c < 4; c++) acc[j][c] = 0.f;

#pragma unroll
    for (int kc = 0; kc < IND / KC; kc++) {
        int k0 = kc * KC;
        __syncthreads();
        for (int i = tid; i < KC * HD; i += 256)
            Wc[i] = W1[k0 * HD + i];
        for (int i = tid; i < 64 * KC; i += 256) {
            int r = i >> 6;
            int kk = i & (KC - 1);
            int row = row0 + r;
            float v = (row < NN) ? h[row * IND + k0 + kk] : 0.f;
            hsT[kk * HSTR + r] = v;
        }
        __syncthreads();

        const float* hp = &hsT[4 * ty];
        const float4* wq = reinterpret_cast<const float4*>(Wc) + tx;
#pragma unroll 8
        for (int kk = 0; kk < KC; kk++) {
            float a0 = hp[0], a1 = hp[1], a2 = hp[2], a3 = hp[3];
            hp += HSTR;
            float4 w = wq[kk * (HD / 4)];
            acc[0][0] = fmaf(a0, w.x, acc[0][0]);
            acc[0][1] = fmaf(a0, w.y, acc[0][1]);
            acc[0][2] = fmaf(a0, w.z, acc[0][2]);
            acc[0][3] = fmaf(a0, w.w, acc[0][3]);
            acc[1][0] = fmaf(a1, w.x, acc[1][0]);
            acc[1][1] = fmaf(a1, w.y, acc[1][1]);
            acc[1][2] = fmaf(a1, w.z, acc[1][2]);
            acc[1][3] = fmaf(a1, w.w, acc[1][3]);
            acc[2][0] = fmaf(a2, w.x, acc[2][0]);
            acc[2][1] = fmaf(a2, w.y, acc[2][1]);
            acc[2][2] = fmaf(a2, w.z, acc[2][2]);
            acc[2][3] = fmaf(a2, w.w, acc[2][3]);
            acc[3][0] = fmaf(a3, w.x, acc[3][0]);
            acc[3][1] = fmaf(a3, w.y, acc[3][1]);
            acc[3][2] = fmaf(a3, w.z, acc[3][2]);
            acc[3][3] = fmaf(a3, w.w, acc[3][3]);
        }
    }

#pragma unroll
    for (int j = 0; j < 4; j++) {
        int row = row0 + 4 * ty + j;
        if (row < NN) {
            float s = g_norm_src[row];
            float4 o = make_float4(acc[j][0] * s, acc[j][1] * s,
                                   acc[j][2] * s, acc[j][3] * s);
            reinterpret_cast<float4*>(g_x1)[row * (HD / 4) + tx] = o;
        }
    }
}

// ============================================================================
// GEMM2: g_x2 = (elu(agg1*norm_dst + b1) * norm_src) @ W2
// ============================================================================
__global__ __launch_bounds__(256) void k_gemm2(const float* __restrict__ b1,
                                               const float* __restrict__ W2) {
    __shared__ __align__(16) float Wc[HD * HD];
    __shared__ float tsT[HD * HSTR];
    __shared__ float b1s[HD];
    int tid = threadIdx.x;
    int ty = tid >> 4;
    int tx = tid & 15;
    int row0 = blockIdx.x * 64;

    for (int i = tid; i < HD * HD; i += 256) Wc[i] = W2[i];
    if (tid < HD) b1s[tid] = b1[tid];
    __syncthreads();

    for (int i = tid; i < 64 * HD; i += 256) {
        int r = i >> 6;
        int k = i & (HD - 1);
        int row = row0 + r;
        float v = 0.f;
        if (row < NN) {
            v = g_agg1[row * HD + k] * g_norm_dst[row] + b1s[k];
            v = (v > 0.f) ? v : expm1f(v);
            v *= g_norm_src[row];
        }
        tsT[k * HSTR + r] = v;
    }
    __syncthreads();

    float acc[4][4];
#pragma unroll
    for (int j = 0; j < 4; j++)
#pragma unroll
        for (int c = 0; c < 4; c++) acc[j][c] = 0.f;

    const float* tp = &tsT[4 * ty];
    const float4* wq = reinterpret_cast<const float4*>(Wc) + tx;
#pragma unroll 8
    for (int k = 0; k < HD; k++) {
        float a0 = tp[0], a1 = tp[1], a2 = tp[2], a3 = tp[3];
        tp += HSTR;
        float4 w = wq[k * (HD / 4)];
        acc[0][0] = fmaf(a0, w.x, acc[0][0]);
        acc[0][1] = fmaf(a0, w.y, acc[0][1]);
        acc[0][2] = fmaf(a0, w.z, acc[0][2]);
        acc[0][3] = fmaf(a0, w.w, acc[0][3]);
        acc[1][0] = fmaf(a1, w.x, acc[1][0]);
        acc[1][1] = fmaf(a1, w.y, acc[1][1]);
        acc[1][2] = fmaf(a1, w.z, acc[1][2]);
        acc[1][3] = fmaf(a1, w.w, acc[1][3]);
        acc[2][0] = fmaf(a2, w.x, acc[2][0]);
        acc[2][1] = fmaf(a2, w.y, acc[2][1]);
        acc[2][2] = fmaf(a2, w.z, acc[2][2]);
        acc[2][3] = fmaf(a2, w.w, acc[2][3]);
        acc[3][0] = fmaf(a3, w.x, acc[3][0]);
        acc[3][1] = fmaf(a3, w.y, acc[3][1]);
        acc[3][2] = fmaf(a3, w.z, acc[3][2]);
        acc[3][3] = fmaf(a3, w.w, acc[3][3]);
    }

#pragma unroll
    for (int j = 0; j < 4; j++) {
        int row = row0 + 4 * ty + j;
        if (row < NN) {
            float4 o = make_float4(acc[j][0], acc[j][1], acc[j][2], acc[j][3]);
            reinterpret_cast<float4*>(g_x2)[row * (HD / 4) + tx] = o;
        }
    }
}

// ============================================================================
// CSR aggregation: warp per node, lane owns float2 of the 64-wide row.
// agg[n] = sum over in-edges of x[src]; no atomics.
// ============================================================================
__device__ __forceinline__ float2 agg_row(const float2* __restrict__ x2,
                                          int n, int lane) {
    int start = g_start[n];
    int deg = g_deg_in[n];
    int end = start + deg;
    float2 acc = make_float2(0.f, 0.f);
    int e = start;
    for (; e + 4 <= end; e += 4) {
        int s0 = __ldg(&g_esrc[e]);
        int s1 = __ldg(&g_esrc[e + 1]);
        int s2 = __ldg(&g_esrc[e + 2]);
        int s3 = __ldg(&g_esrc[e + 3]);
        float2 v0 = __ldg(&x2[s0 * 32 + lane]);
        float2 v1 = __ldg(&x2[s1 * 32 + lane]);
        float2 v2 = __ldg(&x2[s2 * 32 + lane]);
        float2 v3 = __ldg(&x2[s3 * 32 + lane]);
        acc.x += v0.x + v1.x;
        acc.y += v0.y + v1.y;
        acc.x += v2.x + v3.x;
        acc.y += v2.y + v3.y;
    }
    for (; e < end; e++) {
        int s = __ldg(&g_esrc[e]);
        float2 v = __ldg(&x2[s * 32 + lane]);
        acc.x += v.x;
        acc.y += v.y;
    }
    return acc;
}

__global__ __launch_bounds__(256) void k_agg1() {
    int n = (blockIdx.x * 256 + threadIdx.x) >> 5;
    int lane = threadIdx.x & 31;
    if (n >= NN) return;
    float2 acc = agg_row(reinterpret_cast<const float2*>(g_x1), n, lane);
    reinterpret_cast<float2*>(g_agg1)[n * 32 + lane] = acc;
}

// layer-2 aggregation with fused finalize: out = agg*norm_dst + b2
__global__ __launch_bounds__(256) void k_agg2(float* __restrict__ out,
                                              const float* __restrict__ b2) {
    int n = (blockIdx.x * 256 + threadIdx.x) >> 5;
    int lane = threadIdx.x & 31;
    if (n >= NN) return;
    float2 acc = agg_row(reinterpret_cast<const float2*>(g_x2), n, lane);
    float nd = g_norm_dst[n];
    float2 bb = __ldg(reinterpret_cast<const float2*>(b2) + lane);
    float2 o = make_float2(acc.x * nd + bb.x, acc.y * nd + bb.y);
    reinterpret_cast<float2*>(out)[n * 32 + lane] = o;
}

extern "C" void kernel_launch(void* const* d_in, const int* in_sizes, int n_in,
                              void* d_out, int out_size) {
    const float* h   = (const float*)d_in[0];
    const int*   src = (const int*)d_in[1];
    const int*   dst = (const int*)d_in[2];
    const float* W1  = (const float*)d_in[3];
    const float* b1  = (const float*)d_in[4];
    const float* W2  = (const float*)d_in[5];
    const float* b2  = (const float*)d_in[6];
    float* out = (float*)d_out;

    const int GBLK = (NN + 63) / 64;       // 1563
    const int AGG_BLK = (NN * 32 + 255) / 256;  // warp per node

    // ---- graph preprocessing (CSR by dst) ----
    k_init<<<(NN + 255) / 256, 256>>>();
    k_deg<<<(NE + 255) / 256, 256>>>(src, dst);
    k_norm<<<(NN + 255) / 256, 256>>>();
    k_scan1<<<SCAN_BLOCKS, 256>>>();
    k_scan2<<<1, 512>>>();
    k_scan3<<<(NN + 255) / 256, 256>>>();
    k_place<<<(NE + 255) / 256, 256>>>(src, dst);

    // ---- layer 1 ----
    k_gemm1<<<GBLK, 256>>>(h, W1);
    k_agg1<<<AGG_BLK, 256>>>();

    // ---- layer 2 (layer-1 epilogue fused into gemm2; finalize fused into agg2) ----
    k_gemm2<<<GBLK, 256>>>(b1, W2);
    k_agg2<<<AGG_BLK, 256>>>(out, b2);
}